// round 10
// baseline (speedup 1.0000x reference)
#include <cuda_runtime.h>
#include <cstdint>

// Depthwise conv1d, K=7, 'same' padding, softmax over taps — single kernel.
// x: (B, C, T) fp32; weight: (H, 1, 7); head for channel c is c % H (H=16).
//
// R2 tile chassis (best measured kernel: 75.2us / DRAM 80.7%) + softmax
// computed REDUNDANTLY PER WARP via shuffles: no smem broadcast, no barrier
// dependency on warp 0, chain (~470cyc) hides under the tile DRAM loads.

#define KSIZE 7
#define TILE 2048
#define HALF (TILE / 2)
#define THREADS 256
#define SHIFT 4   // s[SHIFT + i] = x[t0 + i]; halo lives at s[1..3]
#define T_LEN 4096
#define FULLMASK 0xFFFFFFFFu

__global__ __launch_bounds__(THREADS)
void lconv1d_kernel(const float* __restrict__ x,
                    const float* __restrict__ wraw,
                    float* __restrict__ out) {
    __shared__ float s[SHIFT + TILE + 3];

    const int row = blockIdx.y;               // b*C + c
    const int t0  = blockIdx.x * TILE;
    const size_t base = (size_t)row * T_LEN + t0;
    const int tid = threadIdx.x;
    const int lane = tid & 31;
    const int p0 = tid * 4;
    const int p1 = p0 + HALF;

    // Issue the two independent main-tile loads first (MLP=2).
    const float4 v0 = *reinterpret_cast<const float4*>(x + base + p0);
    const float4 v1 = *reinterpret_cast<const float4*>(x + base + p1);

    // Halo loads (3 left, 3 right), zero-padded at row boundaries.
    float hl = 0.f, hr = 0.f;
    if (tid < 3) {
        if (t0 > 0)            hl = x[base - 3 + tid];
        if (t0 + TILE < T_LEN) hr = x[base + TILE + tid];
    }

    // Per-warp softmax over the 7 taps (shuffle-parallel; overlaps the LDGs).
    const int h = row & 15;                   // C=1024 multiple of H=16
    float myw = -1e30f;
    if (lane < KSIZE) myw = __ldg(&wraw[h * KSIZE + lane]);
    float m = myw;
    #pragma unroll
    for (int o = 16; o > 0; o >>= 1)
        m = fmaxf(m, __shfl_xor_sync(FULLMASK, m, o));
    float e = (lane < KSIZE) ? __expf(myw - m) : 0.f;
    float sum = e;
    #pragma unroll
    for (int o = 16; o > 0; o >>= 1)
        sum += __shfl_xor_sync(FULLMASK, sum, o);
    const float wk = e / sum;
    const float w0 = __shfl_sync(FULLMASK, wk, 0);
    const float w1 = __shfl_sync(FULLMASK, wk, 1);
    const float w2 = __shfl_sync(FULLMASK, wk, 2);
    const float w3 = __shfl_sync(FULLMASK, wk, 3);
    const float w4 = __shfl_sync(FULLMASK, wk, 4);
    const float w5 = __shfl_sync(FULLMASK, wk, 5);
    const float w6 = __shfl_sync(FULLMASK, wk, 6);

    // Stores into the shared tile (dependent on the LDGs), aligned STS.128.
    *reinterpret_cast<float4*>(&s[SHIFT + p0]) = v0;
    *reinterpret_cast<float4*>(&s[SHIFT + p1]) = v1;
    if (tid < 3) {
        s[1 + tid] = hl;
        s[SHIFT + TILE + tid] = hr;
    }

    __syncthreads();

    // Chunk 0: outputs [p0 .. p0+3]. Middle float4 == v0 (register reuse).
    {
        const float4 a = *reinterpret_cast<const float4*>(&s[p0]);
        const float4 b = v0;
        const float4 c = *reinterpret_cast<const float4*>(&s[p0 + 8]);
        float4 r;
        r.x = w0*a.y + w1*a.z + w2*a.w + w3*b.x + w4*b.y + w5*b.z + w6*b.w;
        r.y = w0*a.z + w1*a.w + w2*b.x + w3*b.y + w4*b.z + w5*b.w + w6*c.x;
        r.z = w0*a.w + w1*b.x + w2*b.y + w3*b.z + w4*b.w + w5*c.x + w6*c.y;
        r.w = w0*b.x + w1*b.y + w2*b.z + w3*b.w + w4*c.x + w5*c.y + w6*c.z;
        *reinterpret_cast<float4*>(out + base + p0) = r;
    }

    // Chunk 1: outputs [p1 .. p1+3]. Middle float4 == v1.
    {
        const float4 a = *reinterpret_cast<const float4*>(&s[p1]);
        const float4 b = v1;
        const float4 c = *reinterpret_cast<const float4*>(&s[p1 + 8]);
        float4 r;
        r.x = w0*a.y + w1*a.z + w2*a.w + w3*b.x + w4*b.y + w5*b.z + w6*b.w;
        r.y = w0*a.z + w1*a.w + w2*b.x + w3*b.y + w4*b.z + w5*b.w + w6*c.x;
        r.z = w0*a.w + w1*b.x + w2*b.y + w3*b.z + w4*b.w + w5*c.x + w6*c.y;
        r.w = w0*b.x + w1*b.y + w2*b.z + w3*b.w + w4*c.x + w5*c.y + w6*c.z;
        *reinterpret_cast<float4*>(out + base + p1) = r;
    }
}

extern "C" void kernel_launch(void* const* d_in, const int* in_sizes, int n_in,
                              void* d_out, int out_size) {
    const float* x = (const float*)d_in[0];
    const float* w = (const float*)d_in[1];
    float* out = (float*)d_out;

    const int rows = in_sizes[0] / T_LEN;   // B*C = 16384

    dim3 grid(T_LEN / TILE, rows);          // (2, 16384)
    lconv1d_kernel<<<grid, THREADS>>>(x, w, out);
}